// round 13
// baseline (speedup 1.0000x reference)
#include <cuda_runtime.h>
#include <cuda_fp16.h>
#include <cstdint>

#define THREADS 256

// ---------------- helpers ----------------
__device__ __forceinline__ uint32_t smem_u32(const void* p){
    uint32_t a;
    asm("{ .reg .u64 t; cvta.to.shared.u64 t, %1; cvt.u32.u64 %0, t; }" : "=r"(a) : "l"(p));
    return a;
}
__device__ __forceinline__ uint32_t packh2(float lo, float hi){
    __half2 h = __floats2half2_rn(lo, hi);
    return *reinterpret_cast<uint32_t*>(&h);
}
__device__ __forceinline__ void mma16816(float d[4], const uint32_t a[4],
                                         const uint32_t b0, const uint32_t b1){
    asm volatile("mma.sync.aligned.m16n8k16.row.col.f32.f16.f16.f32 "
        "{%0,%1,%2,%3}, {%4,%5,%6,%7}, {%8,%9}, {%0,%1,%2,%3};"
        : "+f"(d[0]), "+f"(d[1]), "+f"(d[2]), "+f"(d[3])
        : "r"(a[0]), "r"(a[1]), "r"(a[2]), "r"(a[3]), "r"(b0), "r"(b1));
}
#define CPA16(d, s)  asm volatile("cp.async.cg.shared.global [%0], [%1], 16;" :: "r"(d), "l"(s))
#define CPA_COMMIT() asm volatile("cp.async.commit_group;" ::: "memory")
#define CPA_WAIT0()  asm volatile("cp.async.wait_group 0;" ::: "memory")

// ---------------- merged weights, fp16 fragment-ordered (half2 = uint32) ----------------
// gW01h (stage-1 A operand, M=oo), 16 chunks x 2048 u32, m16n8k16 A-frag order:
//   idx = ((oot*4 + kk)*32 + lane)*4 + ra   (oot = oo tile of 16, [0,4))
//   oo = oot*16 + (lane>>2) + 8*(ra&1); half2 = m = kk*16 + 2*(lane&3) + 8*(ra>>1) + {0,1}
// gW23h (stage-2 A operand, M=o23), same shape:
//   o23 = mt*16 + (lane>>2) + 8*(ra&1); half2 = q = kk*16 + 2*(lane&3) + 8*(ra>>1) + {0,1}
__device__ __align__(16) uint32_t gW01h[32768];
__device__ __align__(16) uint32_t gW23h[32768];

__global__ void tt_pre(const float* __restrict__ w0, const float* __restrict__ w1,
                       const float* __restrict__ w2, const float* __restrict__ w3) {
    int tid = blockIdx.x * blockDim.x + threadIdx.x;
    if (tid < 32768) {
        int c    = tid >> 11;
        int rem  = tid & 2047;
        int ra   = rem & 3;
        int lane = (rem >> 2) & 31;
        int kk   = (rem >> 7) & 3;
        int oot  = rem >> 9;
        int oo   = oot*16 + (lane >> 2) + 8*(ra & 1);
        int mb   = kk*16 + 2*(lane & 3) + 8*(ra >> 1);
        int o0 = oo >> 3, o1 = oo & 7;
        float s[2];
        #pragma unroll
        for (int h = 0; h < 2; h++) {
            int m = mb + h;
            int i0 = m >> 3, i1 = m & 7;
            float v = 0.f;
            #pragma unroll
            for (int r1 = 0; r1 < 16; r1++)
                v += w0[(o0*16 + r1)*8 + i0] * w1[(o1*16 + c)*128 + r1*8 + i1];
            s[h] = v;
        }
        gW01h[c*2048 + rem] = packh2(s[0], s[1]);
    } else if (tid < 65536) {
        int t    = tid - 32768;
        int c    = t >> 11;
        int rem  = t & 2047;
        int ra   = rem & 3;
        int lane = (rem >> 2) & 31;
        int kk   = (rem >> 7) & 3;
        int mt   = rem >> 9;
        int o23  = mt*16 + (lane >> 2) + 8*(ra & 1);
        int qb   = kk*16 + 2*(lane & 3) + 8*(ra >> 1);
        int o2 = o23 >> 3, o3 = o23 & 7;
        float s[2];
        #pragma unroll
        for (int h = 0; h < 2; h++) {
            int q = qb + h;
            int i2 = q >> 3, i3 = q & 7;
            float v = 0.f;
            #pragma unroll
            for (int r3 = 0; r3 < 16; r3++)
                v += w2[(o2*16 + r3)*128 + c*8 + i2] * w3[o3*128 + r3*8 + i3];
            s[h] = v;
        }
        gW23h[c*2048 + rem] = packh2(s[0], s[1]);
    }
}

// ---------------- SMEM map (uint32 indices), 128 KB, 1 CTA/SM ----------------
// XH  [0, 8192)        : X B-fragments fp16 (n=q, k=m), 4 batches x 2048 u32 (bank-swizzled)
// B1H [8192,  +3*4096) : W01 pair-slots (3 slots x 2 chunks x 2048)
// B2H [20480, +3*4096) : W23 pair-slots
#define B1_OFF 8192
#define B2_OFF 20480
#define SMU_TOTAL 32768

__global__ __launch_bounds__(THREADS, 1)
void tt_mma(const float* __restrict__ x, const float* __restrict__ bias,
            float* __restrict__ out) {
    extern __shared__ uint32_t smu[];
    uint32_t* XH  = smu;
    uint32_t* B1H = smu + B1_OFF;
    uint32_t* B2H = smu + B2_OFF;

    const int tid  = threadIdx.x;
    const int wid  = tid >> 5;
    const int lane = tid & 31;
    const uint32_t sb  = smem_u32(smu);
    const uint32_t B1a = sb + B1_OFF*4u;
    const uint32_t B2a = sb + B2_OFF*4u;

    // prologue: prefetch weight pairs 0 and 1 into slots 0,1 (each pair = 1024 uint4 per array)
    #pragma unroll
    for (int p = 0; p < 2; p++) {
        const uint4* s01 = (const uint4*)(gW01h + 2*p*2048);
        const uint4* s23 = (const uint4*)(gW23h + 2*p*2048);
        #pragma unroll
        for (int i = 0; i < 4; i++) CPA16(B1a + p*16384 + (tid + i*256)*16, s01 + tid + i*256);
        #pragma unroll
        for (int i = 0; i < 4; i++) CPA16(B2a + p*16384 + (tid + i*256)*16, s23 + tid + i*256);
        CPA_COMMIT();
    }

    // ---- stage X (4 batch rows) into B-fragment layout in smem ----
    const long long b0 = (long long)blockIdx.x * 4;
    {
        const float4* xp = (const float4*)(x + b0 * 4096);
        #pragma unroll 4
        for (int e = tid; e < 2048; e += THREADS) {
            int u  = e & 31;              // m-pair index: m = 2u, 2u+1
            int qq = (e >> 5) & 15;       // q quad
            int b  = e >> 9;              // batch row (0..3)
            float4 va = xp[b*1024 + (2*u)*16 + qq];
            float4 vb = xp[b*1024 + (2*u + 1)*16 + qq];
            int kk = u >> 3;
            int rb = (u >> 2) & 1;
            int a3 = u & 3;
            float av[4] = {va.x, va.y, va.z, va.w};
            float bv[4] = {vb.x, vb.y, vb.z, vb.w};
            #pragma unroll
            for (int j = 0; j < 4; j++) {
                int q   = qq*4 + j;
                int nt1 = q >> 3;
                int ln  = ((q & 7)*4 + a3 + 8*kk) & 31;   // swizzled physical lane
                XH[(((b*8 + nt1)*4 + kk)*32 + ln)*2 + rb] = packh2(av[j], bv[j]);
            }
        }
    }

    // warp -> (batch bw, oo-half ooh): warp owns FULL q, 32 oo cols
    const int bw  = wid >> 1;
    const int ooh = wid & 1;

    float acc[4][4][4];   // [o23-tile mt][ntl = mt1*2+ntl_in][frag]
    #pragma unroll
    for (int mt = 0; mt < 4; mt++)
        #pragma unroll
        for (int ntl = 0; ntl < 4; ntl++)
            #pragma unroll
            for (int r = 0; r < 4; r++) acc[mt][ntl][r] = 0.f;

    for (int cp = 0; cp < 8; cp++) {          // chunk pairs: chunks 2cp, 2cp+1
        const int s = cp % 3;                 // pair slot
        CPA_WAIT0();
        __syncthreads();   // cp.async data CTA-visible; WAR on slot (cp+2)%3 cleared

        if (cp < 6) {      // prefetch pair cp+2 into slot (cp+2)%3
            const int ns = (cp + 2) % 3;
            const uint4* s01 = (const uint4*)(gW01h + 2*(cp + 2)*2048);
            const uint4* s23 = (const uint4*)(gW23h + 2*(cp + 2)*2048);
            #pragma unroll
            for (int i = 0; i < 4; i++) CPA16(B1a + ns*16384 + (tid + i*256)*16, s01 + tid + i*256);
            #pragma unroll
            for (int i = 0; i < 4; i++) CPA16(B2a + ns*16384 + (tid + i*256)*16, s23 + tid + i*256);
            CPA_COMMIT();
        }

        const uint32_t* W01s = B1H + s*4096;   // chunk a at +0, chunk b at +2048
        const uint32_t* W23s = B2H + s*4096;

        // ---- stage 1 for BOTH chunks: dT[oo(32) x q(64)], X LDS shared per kk ----
        float d[2][2][8][4];   // [chunk][mt1][nt1][frag]
        #pragma unroll
        for (int ch = 0; ch < 2; ch++)
            #pragma unroll
            for (int mt1 = 0; mt1 < 2; mt1++)
                #pragma unroll
                for (int nt1 = 0; nt1 < 8; nt1++)
                    #pragma unroll
                    for (int r = 0; r < 4; r++) d[ch][mt1][nt1][r] = 0.f;

        #pragma unroll
        for (int kk = 0; kk < 4; kk++) {
            const int ln = (lane + 8*kk) & 31;
            uint32_t xb[8][2];
            #pragma unroll
            for (int nt1 = 0; nt1 < 8; nt1++) {
                uint2 bf = *(const uint2*)(XH + (((bw*8 + nt1)*4 + kk)*32 + ln)*2);
                xb[nt1][0] = bf.x; xb[nt1][1] = bf.y;
            }
            #pragma unroll
            for (int ch = 0; ch < 2; ch++)
                #pragma unroll
                for (int mt1 = 0; mt1 < 2; mt1++) {
                    const int oot = ooh*2 + mt1;
                    uint4 af = *(const uint4*)(W01s + ch*2048 + ((oot*4 + kk)*32 + lane)*4);
                    uint32_t a[4] = {af.x, af.y, af.z, af.w};
                    #pragma unroll
                    for (int nt1 = 0; nt1 < 8; nt1++)
                        mma16816(d[ch][mt1][nt1], a, xb[nt1][0], xb[nt1][1]);
                }
        }

        // ---- stage 2 for both chunks: ACC += W23(A) @ dT(B from C-frags) ----
        #pragma unroll
        for (int ch = 0; ch < 2; ch++) {
            const uint32_t* W23c = W23s + ch*2048;
            #pragma unroll
            for (int K = 0; K < 4; K++) {
                uint32_t bs[4][2];
                #pragma unroll
                for (int mt1 = 0; mt1 < 2; mt1++) {
                    bs[mt1*2 + 0][0] = packh2(d[ch][mt1][2*K][0],     d[ch][mt1][2*K][1]);
                    bs[mt1*2 + 0][1] = packh2(d[ch][mt1][2*K + 1][0], d[ch][mt1][2*K + 1][1]);
                    bs[mt1*2 + 1][0] = packh2(d[ch][mt1][2*K][2],     d[ch][mt1][2*K][3]);
                    bs[mt1*2 + 1][1] = packh2(d[ch][mt1][2*K + 1][2], d[ch][mt1][2*K + 1][3]);
                }
                #pragma unroll
                for (int mt = 0; mt < 4; mt++) {
                    uint4 af = *(const uint4*)(W23c + ((mt*4 + K)*32 + lane)*4);
                    uint32_t a[4] = {af.x, af.y, af.z, af.w};
                    #pragma unroll
                    for (int ntl = 0; ntl < 4; ntl++)
                        mma16816(acc[mt][ntl], a, bs[ntl][0], bs[ntl][1]);
                }
            }
        }
    }

    // ---- epilogue: acc element (row=o23, col=oo) + bias -> out ----
    {
        const int g = lane >> 2, tq = lane & 3;
        float* ob = out + (b0 + bw) * 4096;
        #pragma unroll
        for (int mt = 0; mt < 4; mt++)
            #pragma unroll
            for (int ntl = 0; ntl < 4; ntl++)
                #pragma unroll
                for (int r = 0; r < 4; r++) {
                    int o23 = mt*16 + g + 8*(r >> 1);
                    int oo  = ooh*32 + ntl*8 + 2*tq + (r & 1);
                    int col = oo*64 + o23;
                    ob[col] = acc[mt][ntl][r] + __ldg(bias + col);
                }
    }
}

extern "C" void kernel_launch(void* const* d_in, const int* in_sizes, int n_in,
                              void* d_out, int out_size) {
    const float* x    = (const float*)d_in[0];
    const float* w0   = (const float*)d_in[1];
    const float* w1   = (const float*)d_in[2];
    const float* w2   = (const float*)d_in[3];
    const float* w3   = (const float*)d_in[4];
    const float* bias = (const float*)d_in[5];
    float* out = (float*)d_out;

    tt_pre<<<256, 256>>>(w0, w1, w2, w3);

    cudaFuncSetAttribute(tt_mma, cudaFuncAttributeMaxDynamicSharedMemorySize,
                         SMU_TOTAL * (int)sizeof(uint32_t));
    tt_mma<<<16384 / 4, THREADS, SMU_TOTAL * (int)sizeof(uint32_t)>>>(x, bias, out);
}

// round 14
// speedup vs baseline: 1.0347x; 1.0347x over previous
#include <cuda_runtime.h>
#include <cuda_fp16.h>
#include <cstdint>

#define THREADS 256

// ---------------- helpers ----------------
__device__ __forceinline__ uint32_t smem_u32(const void* p){
    uint32_t a;
    asm("{ .reg .u64 t; cvta.to.shared.u64 t, %1; cvt.u32.u64 %0, t; }" : "=r"(a) : "l"(p));
    return a;
}
__device__ __forceinline__ uint32_t packh2(float lo, float hi){
    __half2 h = __floats2half2_rn(lo, hi);
    return *reinterpret_cast<uint32_t*>(&h);
}
__device__ __forceinline__ void mma16816(float d[4], const uint32_t a[4],
                                         const uint32_t b0, const uint32_t b1){
    asm volatile("mma.sync.aligned.m16n8k16.row.col.f32.f16.f16.f32 "
        "{%0,%1,%2,%3}, {%4,%5,%6,%7}, {%8,%9}, {%0,%1,%2,%3};"
        : "+f"(d[0]), "+f"(d[1]), "+f"(d[2]), "+f"(d[3])
        : "r"(a[0]), "r"(a[1]), "r"(a[2]), "r"(a[3]), "r"(b0), "r"(b1));
}
#define CPA16(d, s)  asm volatile("cp.async.cg.shared.global [%0], [%1], 16;" :: "r"(d), "l"(s))
#define CPA_COMMIT() asm volatile("cp.async.commit_group;" ::: "memory")
#define CPA_WAIT0()  asm volatile("cp.async.wait_group 0;" ::: "memory")
#define CPA_WAIT1()  asm volatile("cp.async.wait_group 1;" ::: "memory")

// ---------------- merged weights, fp16 fragment-ordered (half2 = uint32) ----------------
// gW01h (stage-1 A operand, M=oo), 16 chunks x 2048 u32, m16n8k16 A-frag order:
//   idx = ((oot*4 + kk)*32 + lane)*4 + ra   (oot = oo tile of 16, [0,4))
//   oo = oot*16 + (lane>>2) + 8*(ra&1); half2 = m = kk*16 + 2*(lane&3) + 8*(ra>>1) + {0,1}
// gW23h (stage-2 A operand, M=o23), same shape:
//   o23 = mt*16 + (lane>>2) + 8*(ra&1); half2 = q = kk*16 + 2*(lane&3) + 8*(ra>>1) + {0,1}
__device__ __align__(16) uint32_t gW01h[32768];
__device__ __align__(16) uint32_t gW23h[32768];

__global__ void tt_pre(const float* __restrict__ w0, const float* __restrict__ w1,
                       const float* __restrict__ w2, const float* __restrict__ w3) {
    int tid = blockIdx.x * blockDim.x + threadIdx.x;
    if (tid < 32768) {
        int c    = tid >> 11;
        int rem  = tid & 2047;
        int ra   = rem & 3;
        int lane = (rem >> 2) & 31;
        int kk   = (rem >> 7) & 3;
        int oot  = rem >> 9;
        int oo   = oot*16 + (lane >> 2) + 8*(ra & 1);
        int mb   = kk*16 + 2*(lane & 3) + 8*(ra >> 1);
        int o0 = oo >> 3, o1 = oo & 7;
        float s[2];
        #pragma unroll
        for (int h = 0; h < 2; h++) {
            int m = mb + h;
            int i0 = m >> 3, i1 = m & 7;
            float v = 0.f;
            #pragma unroll
            for (int r1 = 0; r1 < 16; r1++)
                v += w0[(o0*16 + r1)*8 + i0] * w1[(o1*16 + c)*128 + r1*8 + i1];
            s[h] = v;
        }
        gW01h[c*2048 + rem] = packh2(s[0], s[1]);
    } else if (tid < 65536) {
        int t    = tid - 32768;
        int c    = t >> 11;
        int rem  = t & 2047;
        int ra   = rem & 3;
        int lane = (rem >> 2) & 31;
        int kk   = (rem >> 7) & 3;
        int mt   = rem >> 9;
        int o23  = mt*16 + (lane >> 2) + 8*(ra & 1);
        int qb   = kk*16 + 2*(lane & 3) + 8*(ra >> 1);
        int o2 = o23 >> 3, o3 = o23 & 7;
        float s[2];
        #pragma unroll
        for (int h = 0; h < 2; h++) {
            int q = qb + h;
            int i2 = q >> 3, i3 = q & 7;
            float v = 0.f;
            #pragma unroll
            for (int r3 = 0; r3 < 16; r3++)
                v += w2[(o2*16 + r3)*128 + c*8 + i2] * w3[o3*128 + r3*8 + i3];
            s[h] = v;
        }
        gW23h[c*2048 + rem] = packh2(s[0], s[1]);
    }
}

// ---------------- SMEM map (uint32 indices), 160 KB, 1 CTA/SM ----------------
// XH [0, 8192)       : X B-fragments fp16 (bank-swizzled), 4 batches x 2048 u32
// WH [8192, +32768)  : 8 chunk-slots x 4096 u32 (W01 chunk at +0, W23 chunk at +2048)
#define W_OFF 8192
#define SMU_TOTAL 40960

__global__ __launch_bounds__(THREADS, 1)
void tt_mma(const float* __restrict__ x, const float* __restrict__ bias,
            float* __restrict__ out) {
    extern __shared__ uint32_t smu[];
    uint32_t* XH = smu;
    uint32_t* WH = smu + W_OFF;

    const int tid  = threadIdx.x;
    const int wid  = tid >> 5;
    const int lane = tid & 31;
    const uint32_t sb = smem_u32(smu);
    const uint32_t Wa = sb + W_OFF*4u;

    // ---- prologue: issue weight windows 0 (chunks 0-3) and 1 (chunks 4-7) ----
    #pragma unroll
    for (int w = 0; w < 2; w++) {
        #pragma unroll
        for (int cc = 0; cc < 4; cc++) {
            const int c = w*4 + cc;           // slot = c (c < 8)
            const uint4* s01 = (const uint4*)(gW01h + c*2048);
            const uint4* s23 = (const uint4*)(gW23h + c*2048);
            #pragma unroll
            for (int i = 0; i < 2; i++) {
                CPA16(Wa + c*16384u + (tid + i*256)*16, s01 + tid + i*256);
                CPA16(Wa + c*16384u + 8192u + (tid + i*256)*16, s23 + tid + i*256);
            }
        }
        CPA_COMMIT();
    }

    // ---- stage X (4 batch rows) into B-fragment layout in smem ----
    const long long b0 = (long long)blockIdx.x * 4;
    {
        const float4* xp = (const float4*)(x + b0 * 4096);
        #pragma unroll 4
        for (int e = tid; e < 2048; e += THREADS) {
            int u  = e & 31;              // m-pair index: m = 2u, 2u+1
            int qq = (e >> 5) & 15;       // q quad
            int b  = e >> 9;              // batch row (0..3)
            float4 va = xp[b*1024 + (2*u)*16 + qq];
            float4 vb = xp[b*1024 + (2*u + 1)*16 + qq];
            int kk = u >> 3;
            int rb = (u >> 2) & 1;
            int a3 = u & 3;
            float av[4] = {va.x, va.y, va.z, va.w};
            float bv[4] = {vb.x, vb.y, vb.z, vb.w};
            #pragma unroll
            for (int j = 0; j < 4; j++) {
                int q   = qq*4 + j;
                int nt1 = q >> 3;
                int ln  = ((q & 7)*4 + a3 + 8*kk) & 31;   // swizzled physical lane
                XH[(((b*8 + nt1)*4 + kk)*32 + ln)*2 + rb] = packh2(av[j], bv[j]);
            }
        }
    }

    CPA_WAIT1();        // window 0 weights complete (window 1 may be in flight)
    __syncthreads();    // X + window-0 weights visible CTA-wide

    // warp -> (batch bw, oo-half ooh): warp owns FULL q, 32 oo cols
    const int bw  = wid >> 1;
    const int ooh = wid & 1;

    // ---- this warp's X B-fragments in registers (chunk-invariant) ----
    uint32_t xr[4][8][2];
    #pragma unroll
    for (int kk = 0; kk < 4; kk++) {
        const int ln = (lane + 8*kk) & 31;
        #pragma unroll
        for (int nt1 = 0; nt1 < 8; nt1++) {
            uint2 bf = *(const uint2*)(XH + (((bw*8 + nt1)*4 + kk)*32 + ln)*2);
            xr[kk][nt1][0] = bf.x;
            xr[kk][nt1][1] = bf.y;
        }
    }

    float acc[4][4][4];
    #pragma unroll
    for (int mt = 0; mt < 4; mt++)
        #pragma unroll
        for (int ntl = 0; ntl < 4; ntl++)
            #pragma unroll
            for (int r = 0; r < 4; r++) acc[mt][ntl][r] = 0.f;

    for (int c = 0; c < 16; c++) {
        const uint32_t* W01s = WH + (c & 7)*4096;
        const uint32_t* W23s = W01s + 2048;

        // ---- stage 1: dT[oo(32) x q(64)] = W01_c(A) @ X(B, registers) ----
        float d[2][8][4];
        #pragma unroll
        for (int mt1 = 0; mt1 < 2; mt1++)
            #pragma unroll
            for (int nt1 = 0; nt1 < 8; nt1++)
                #pragma unroll
                for (int r = 0; r < 4; r++) d[mt1][nt1][r] = 0.f;

        #pragma unroll
        for (int kk = 0; kk < 4; kk++) {
            #pragma unroll
            for (int mt1 = 0; mt1 < 2; mt1++) {
                const int oot = ooh*2 + mt1;
                uint4 af = *(const uint4*)(W01s + ((oot*4 + kk)*32 + lane)*4);
                uint32_t a[4] = {af.x, af.y, af.z, af.w};
                #pragma unroll
                for (int nt1 = 0; nt1 < 8; nt1++)
                    mma16816(d[mt1][nt1], a, xr[kk][nt1][0], xr[kk][nt1][1]);
            }
        }

        // ---- stage 2: ACC[o23(64) x oo(32)] += W23_c(A) @ dT(B from C-frags) ----
        #pragma unroll
        for (int K = 0; K < 4; K++) {
            uint32_t bs[4][2];
            #pragma unroll
            for (int mt1 = 0; mt1 < 2; mt1++) {
                bs[mt1*2 + 0][0] = packh2(d[mt1][2*K][0],     d[mt1][2*K][1]);
                bs[mt1*2 + 0][1] = packh2(d[mt1][2*K + 1][0], d[mt1][2*K + 1][1]);
                bs[mt1*2 + 1][0] = packh2(d[mt1][2*K][2],     d[mt1][2*K][3]);
                bs[mt1*2 + 1][1] = packh2(d[mt1][2*K + 1][2], d[mt1][2*K + 1][3]);
            }
            #pragma unroll
            for (int mt = 0; mt < 4; mt++) {
                uint4 af = *(const uint4*)(W23s + ((mt*4 + K)*32 + lane)*4);
                uint32_t a[4] = {af.x, af.y, af.z, af.w};
                #pragma unroll
                for (int ntl = 0; ntl < 4; ntl++)
                    mma16816(acc[mt][ntl], a, bs[ntl][0], bs[ntl][1]);
            }
        }

        // ---- window boundary (every 4 chunks): ONE barrier, then batch-issue ----
        if ((c & 3) == 3 && c < 15) {
            CPA_WAIT0();        // next window's weights fully arrived
            __syncthreads();    // visibility + WAR: this window's slots now free
            if (c < 11) {       // issue window (c+5)/4 + ... = chunks c+5 .. c+8
                #pragma unroll
                for (int cc = 0; cc < 4; cc++) {
                    const int nc = c + 5 + cc;
                    const int sl = nc & 7;
                    const uint4* s01 = (const uint4*)(gW01h + nc*2048);
                    const uint4* s23 = (const uint4*)(gW23h + nc*2048);
                    #pragma unroll
                    for (int i = 0; i < 2; i++) {
                        CPA16(Wa + sl*16384u + (tid + i*256)*16, s01 + tid + i*256);
                        CPA16(Wa + sl*16384u + 8192u + (tid + i*256)*16, s23 + tid + i*256);
                    }
                }
                CPA_COMMIT();
            }
        }
    }

    // ---- epilogue: acc element (row=o23, col=oo) + bias -> out ----
    {
        const int g = lane >> 2, tq = lane & 3;
        float* ob = out + (b0 + bw) * 4096;
        #pragma unroll
        for (int mt = 0; mt < 4; mt++)
            #pragma unroll
            for (int ntl = 0; ntl < 4; ntl++)
                #pragma unroll
                for (int r = 0; r < 4; r++) {
                    int o23 = mt*16 + g + 8*(r >> 1);
                    int oo  = ooh*32 + ntl*8 + 2*tq + (r & 1);
                    int col = oo*64 + o23;
                    ob[col] = acc[mt][ntl][r] + __ldg(bias + col);
                }
    }
}

extern "C" void kernel_launch(void* const* d_in, const int* in_sizes, int n_in,
                              void* d_out, int out_size) {
    const float* x    = (const float*)d_in[0];
    const float* w0   = (const float*)d_in[1];
    const float* w1   = (const float*)d_in[2];
    const float* w2   = (const float*)d_in[3];
    const float* w3   = (const float*)d_in[4];
    const float* bias = (const float*)d_in[5];
    float* out = (float*)d_out;

    tt_pre<<<256, 256>>>(w0, w1, w2, w3);

    cudaFuncSetAttribute(tt_mma, cudaFuncAttributeMaxDynamicSharedMemorySize,
                         SMU_TOTAL * (int)sizeof(uint32_t));
    tt_mma<<<16384 / 4, THREADS, SMU_TOTAL * (int)sizeof(uint32_t)>>>(x, bias, out);
}

// round 15
// speedup vs baseline: 1.0554x; 1.0200x over previous
#include <cuda_runtime.h>
#include <cuda_fp16.h>
#include <cstdint>

#define THREADS 256

// ---------------- helpers ----------------
__device__ __forceinline__ uint32_t smem_u32(const void* p){
    uint32_t a;
    asm("{ .reg .u64 t; cvta.to.shared.u64 t, %1; cvt.u32.u64 %0, t; }" : "=r"(a) : "l"(p));
    return a;
}
__device__ __forceinline__ uint32_t packh2(float lo, float hi){
    __half2 h = __floats2half2_rn(lo, hi);
    return *reinterpret_cast<uint32_t*>(&h);
}
__device__ __forceinline__ void mma16816(float d[4], const uint32_t a[4],
                                         const uint32_t b0, const uint32_t b1){
    asm volatile("mma.sync.aligned.m16n8k16.row.col.f32.f16.f16.f32 "
        "{%0,%1,%2,%3}, {%4,%5,%6,%7}, {%8,%9}, {%0,%1,%2,%3};"
        : "+f"(d[0]), "+f"(d[1]), "+f"(d[2]), "+f"(d[3])
        : "r"(a[0]), "r"(a[1]), "r"(a[2]), "r"(a[3]), "r"(b0), "r"(b1));
}
#define CPA16(d, s)  asm volatile("cp.async.cg.shared.global [%0], [%1], 16;" :: "r"(d), "l"(s))
#define CPA_COMMIT() asm volatile("cp.async.commit_group;" ::: "memory")
#define CPA_WAIT0()  asm volatile("cp.async.wait_group 0;" ::: "memory")
#define CPA_WAIT1()  asm volatile("cp.async.wait_group 1;" ::: "memory")

// ---------------- merged weights, fp16 fragment-ordered (half2 = uint32) ----------------
// gW01h (stage-1 A operand, M=oo), 16 chunks x 2048 u32, m16n8k16 A-frag order:
//   idx = ((oot*4 + kk)*32 + lane)*4 + ra   (oot = oo tile of 16, [0,4))
//   oo = oot*16 + (lane>>2) + 8*(ra&1); half2 = m = kk*16 + 2*(lane&3) + 8*(ra>>1) + {0,1}
// gW23h (stage-2 A operand, M=o23), same shape:
//   o23 = mt*16 + (lane>>2) + 8*(ra&1); half2 = q = kk*16 + 2*(lane&3) + 8*(ra>>1) + {0,1}
__device__ __align__(16) uint32_t gW01h[32768];
__device__ __align__(16) uint32_t gW23h[32768];

__global__ void tt_pre(const float* __restrict__ w0, const float* __restrict__ w1,
                       const float* __restrict__ w2, const float* __restrict__ w3) {
    int tid = blockIdx.x * blockDim.x + threadIdx.x;
    if (tid < 32768) {
        int c    = tid >> 11;
        int rem  = tid & 2047;
        int ra   = rem & 3;
        int lane = (rem >> 2) & 31;
        int kk   = (rem >> 7) & 3;
        int oot  = rem >> 9;
        int oo   = oot*16 + (lane >> 2) + 8*(ra & 1);
        int mb   = kk*16 + 2*(lane & 3) + 8*(ra >> 1);
        int o0 = oo >> 3, o1 = oo & 7;
        float s[2];
        #pragma unroll
        for (int h = 0; h < 2; h++) {
            int m = mb + h;
            int i0 = m >> 3, i1 = m & 7;
            float v = 0.f;
            #pragma unroll
            for (int r1 = 0; r1 < 16; r1++)
                v += w0[(o0*16 + r1)*8 + i0] * w1[(o1*16 + c)*128 + r1*8 + i1];
            s[h] = v;
        }
        gW01h[c*2048 + rem] = packh2(s[0], s[1]);
    } else if (tid < 65536) {
        int t    = tid - 32768;
        int c    = t >> 11;
        int rem  = t & 2047;
        int ra   = rem & 3;
        int lane = (rem >> 2) & 31;
        int kk   = (rem >> 7) & 3;
        int mt   = rem >> 9;
        int o23  = mt*16 + (lane >> 2) + 8*(ra & 1);
        int qb   = kk*16 + 2*(lane & 3) + 8*(ra >> 1);
        int o2 = o23 >> 3, o3 = o23 & 7;
        float s[2];
        #pragma unroll
        for (int h = 0; h < 2; h++) {
            int q = qb + h;
            int i2 = q >> 3, i3 = q & 7;
            float v = 0.f;
            #pragma unroll
            for (int r3 = 0; r3 < 16; r3++)
                v += w2[(o2*16 + r3)*128 + c*8 + i2] * w3[o3*128 + r3*8 + i3];
            s[h] = v;
        }
        gW23h[c*2048 + rem] = packh2(s[0], s[1]);
    }
}

// ---------------- SMEM map (uint32 indices), 160 KB, 1 CTA/SM ----------------
// XH [0, 8192)       : X B-fragments fp16 (bank-swizzled), 4 batches x 2048 u32
// WH [8192, +32768)  : 8 chunk-slots x 4096 u32 (W01 at +0, W23 at +2048)
//                      reused post-loop as per-warp epilogue staging (2176 floats/warp)
#define W_OFF 8192
#define SMU_TOTAL 40960

__global__ __launch_bounds__(THREADS, 1)
void tt_mma(const float* __restrict__ x, const float* __restrict__ bias,
            float* __restrict__ out) {
    extern __shared__ uint32_t smu[];
    uint32_t* XH = smu;
    uint32_t* WH = smu + W_OFF;

    const int tid  = threadIdx.x;
    const int wid  = tid >> 5;
    const int lane = tid & 31;
    const uint32_t sb = smem_u32(smu);
    const uint32_t Wa = sb + W_OFF*4u;

    // ---- prologue: issue weight windows 0 (chunks 0-3) and 1 (chunks 4-7) ----
    #pragma unroll
    for (int w = 0; w < 2; w++) {
        #pragma unroll
        for (int cc = 0; cc < 4; cc++) {
            const int c = w*4 + cc;           // slot = c (c < 8)
            const uint4* s01 = (const uint4*)(gW01h + c*2048);
            const uint4* s23 = (const uint4*)(gW23h + c*2048);
            #pragma unroll
            for (int i = 0; i < 2; i++) {
                CPA16(Wa + c*16384u + (tid + i*256)*16, s01 + tid + i*256);
                CPA16(Wa + c*16384u + 8192u + (tid + i*256)*16, s23 + tid + i*256);
            }
        }
        CPA_COMMIT();
    }

    // ---- stage X (4 batch rows) into B-fragment layout in smem ----
    const long long b0 = (long long)blockIdx.x * 4;
    {
        const float4* xp = (const float4*)(x + b0 * 4096);
        #pragma unroll 4
        for (int e = tid; e < 2048; e += THREADS) {
            int u  = e & 31;              // m-pair index: m = 2u, 2u+1
            int qq = (e >> 5) & 15;       // q quad
            int b  = e >> 9;              // batch row (0..3)
            float4 va = xp[b*1024 + (2*u)*16 + qq];
            float4 vb = xp[b*1024 + (2*u + 1)*16 + qq];
            int kk = u >> 3;
            int rb = (u >> 2) & 1;
            int a3 = u & 3;
            float av[4] = {va.x, va.y, va.z, va.w};
            float bv[4] = {vb.x, vb.y, vb.z, vb.w};
            #pragma unroll
            for (int j = 0; j < 4; j++) {
                int q   = qq*4 + j;
                int nt1 = q >> 3;
                int ln  = ((q & 7)*4 + a3 + 8*kk) & 31;   // swizzled physical lane
                XH[(((b*8 + nt1)*4 + kk)*32 + ln)*2 + rb] = packh2(av[j], bv[j]);
            }
        }
    }

    CPA_WAIT1();        // window 0 weights complete (window 1 may be in flight)
    __syncthreads();    // X + window-0 weights visible CTA-wide

    // warp -> (batch bw, oo-half ooh): warp owns FULL q, 32 oo cols
    const int bw  = wid >> 1;
    const int ooh = wid & 1;
    const int rot = (wid & 1) << 1;     // odd warps rotate window order by 2

    // ---- this warp's X B-fragments in registers (chunk-invariant) ----
    uint32_t xr[4][8][2];
    #pragma unroll
    for (int kk = 0; kk < 4; kk++) {
        const int ln = (lane + 8*kk) & 31;
        #pragma unroll
        for (int nt1 = 0; nt1 < 8; nt1++) {
            uint2 bf = *(const uint2*)(XH + (((bw*8 + nt1)*4 + kk)*32 + ln)*2);
            xr[kk][nt1][0] = bf.x;
            xr[kk][nt1][1] = bf.y;
        }
    }

    float acc[4][4][4];
    #pragma unroll
    for (int mt = 0; mt < 4; mt++)
        #pragma unroll
        for (int ntl = 0; ntl < 4; ntl++)
            #pragma unroll
            for (int r = 0; r < 4; r++) acc[mt][ntl][r] = 0.f;

    for (int ci = 0; ci < 16; ci++) {
        // stagger: odd warps process the 4-chunk window in rotated order (2,3,0,1)
        const int c = (ci & ~3) | ((ci + rot) & 3);
        const uint32_t* W01s = WH + (c & 7)*4096;
        const uint32_t* W23s = W01s + 2048;

        // ---- stage 1: dT[oo(32) x q(64)] = W01_c(A) @ X(B, registers) ----
        float d[2][8][4];
        #pragma unroll
        for (int mt1 = 0; mt1 < 2; mt1++)
            #pragma unroll
            for (int nt1 = 0; nt1 < 8; nt1++)
                #pragma unroll
                for (int r = 0; r < 4; r++) d[mt1][nt1][r] = 0.f;

        #pragma unroll
        for (int kk = 0; kk < 4; kk++) {
            #pragma unroll
            for (int mt1 = 0; mt1 < 2; mt1++) {
                const int oot = ooh*2 + mt1;
                uint4 af = *(const uint4*)(W01s + ((oot*4 + kk)*32 + lane)*4);
                uint32_t a[4] = {af.x, af.y, af.z, af.w};
                #pragma unroll
                for (int nt1 = 0; nt1 < 8; nt1++)
                    mma16816(d[mt1][nt1], a, xr[kk][nt1][0], xr[kk][nt1][1]);
            }
        }

        // ---- stage 2: ACC[o23(64) x oo(32)] += W23_c(A) @ dT(B from C-frags) ----
        #pragma unroll
        for (int K = 0; K < 4; K++) {
            // preload all 4 af first: LDS latency hides under the packs
            uint4 af[4];
            #pragma unroll
            for (int mt = 0; mt < 4; mt++)
                af[mt] = *(const uint4*)(W23s + ((mt*4 + K)*32 + lane)*4);
            uint32_t bs[4][2];
            #pragma unroll
            for (int mt1 = 0; mt1 < 2; mt1++) {
                bs[mt1*2 + 0][0] = packh2(d[mt1][2*K][0],     d[mt1][2*K][1]);
                bs[mt1*2 + 0][1] = packh2(d[mt1][2*K + 1][0], d[mt1][2*K + 1][1]);
                bs[mt1*2 + 1][0] = packh2(d[mt1][2*K][2],     d[mt1][2*K][3]);
                bs[mt1*2 + 1][1] = packh2(d[mt1][2*K + 1][2], d[mt1][2*K + 1][3]);
            }
            #pragma unroll
            for (int mt = 0; mt < 4; mt++) {
                uint32_t a[4] = {af[mt].x, af[mt].y, af[mt].z, af[mt].w};
                #pragma unroll
                for (int ntl = 0; ntl < 4; ntl++)
                    mma16816(acc[mt][ntl], a, bs[ntl][0], bs[ntl][1]);
            }
        }

        // ---- window boundary (every 4 chunks): ONE barrier, then batch-issue ----
        if ((ci & 3) == 3 && ci < 15) {
            CPA_WAIT0();        // next window's weights fully arrived
            __syncthreads();    // visibility + WAR: this window's slots now free
            if (ci < 11) {      // issue chunks ci+5 .. ci+8
                #pragma unroll
                for (int cc = 0; cc < 4; cc++) {
                    const int nc = ci + 5 + cc;
                    const int sl = nc & 7;
                    const uint4* s01 = (const uint4*)(gW01h + nc*2048);
                    const uint4* s23 = (const uint4*)(gW23h + nc*2048);
                    #pragma unroll
                    for (int i = 0; i < 2; i++) {
                        CPA16(Wa + sl*16384u + (tid + i*256)*16, s01 + tid + i*256);
                        CPA16(Wa + sl*16384u + 8192u + (tid + i*256)*16, s23 + tid + i*256);
                    }
                }
                CPA_COMMIT();
            }
        }
    }

    // ---- epilogue: per-warp smem transpose (stride 68, conflict-free), coalesced STG ----
    {
        const int g = lane >> 2, tq = lane & 3;
        float* epi = (float*)WH + wid * 2176;   // 8 warps x 2176 floats = 68 KB < 128 KB
        #pragma unroll
        for (int mt = 0; mt < 4; mt++)
            #pragma unroll
            for (int ntl = 0; ntl < 4; ntl++)
                #pragma unroll
                for (int r = 0; r < 4; r++) {
                    int o23 = mt*16 + g + 8*(r >> 1);
                    int ool = ntl*8 + 2*tq + (r & 1);
                    epi[ool*68 + o23] = acc[mt][ntl][r];
                }
        __syncwarp();
        float* ob = out + (b0 + bw) * 4096 + ooh * 2048;
        const float* bb = bias + ooh * 2048;
        #pragma unroll
        for (int i = 0; i < 16; i++) {
            int f = i*128 + lane*4;
            float4 v  = *(const float4*)(epi + f + 4*(f >> 6));
            float4 bv = *(const float4*)(bb + f);
            v.x += bv.x; v.y += bv.y; v.z += bv.z; v.w += bv.w;
            *(float4*)(ob + f) = v;
        }
    }
}

extern "C" void kernel_launch(void* const* d_in, const int* in_sizes, int n_in,
                              void* d_out, int out_size) {
    const float* x    = (const float*)d_in[0];
    const float* w0   = (const float*)d_in[1];
    const float* w1   = (const float*)d_in[2];
    const float* w2   = (const float*)d_in[3];
    const float* w3   = (const float*)d_in[4];
    const float* bias = (const float*)d_in[5];
    float* out = (float*)d_out;

    tt_pre<<<256, 256>>>(w0, w1, w2, w3);

    cudaFuncSetAttribute(tt_mma, cudaFuncAttributeMaxDynamicSharedMemorySize,
                         SMU_TOTAL * (int)sizeof(uint32_t));
    tt_mma<<<16384 / 4, THREADS, SMU_TOTAL * (int)sizeof(uint32_t)>>>(x, bias, out);
}

// round 16
// speedup vs baseline: 1.2122x; 1.1486x over previous
#include <cuda_runtime.h>
#include <cuda_fp16.h>
#include <cstdint>

#define THREADS 128

// ---------------- helpers ----------------
__device__ __forceinline__ uint32_t smem_u32(const void* p){
    uint32_t a;
    asm("{ .reg .u64 t; cvta.to.shared.u64 t, %1; cvt.u32.u64 %0, t; }" : "=r"(a) : "l"(p));
    return a;
}
__device__ __forceinline__ uint32_t packh2(float lo, float hi){
    __half2 h = __floats2half2_rn(lo, hi);
    return *reinterpret_cast<uint32_t*>(&h);
}
__device__ __forceinline__ void mma16816(float d[4], const uint32_t a[4],
                                         const uint32_t b0, const uint32_t b1){
    asm volatile("mma.sync.aligned.m16n8k16.row.col.f32.f16.f16.f32 "
        "{%0,%1,%2,%3}, {%4,%5,%6,%7}, {%8,%9}, {%0,%1,%2,%3};"
        : "+f"(d[0]), "+f"(d[1]), "+f"(d[2]), "+f"(d[3])
        : "r"(a[0]), "r"(a[1]), "r"(a[2]), "r"(a[3]), "r"(b0), "r"(b1));
}
#define CPA16(d, s)  asm volatile("cp.async.cg.shared.global [%0], [%1], 16;" :: "r"(d), "l"(s))
#define CPA_COMMIT() asm volatile("cp.async.commit_group;" ::: "memory")
#define CPA_WAIT0()  asm volatile("cp.async.wait_group 0;" ::: "memory")
#define CPA_WAIT1()  asm volatile("cp.async.wait_group 1;" ::: "memory")

// ---------------- merged weights, fp16 fragment-ordered (half2 = uint32) ----------------
// gW01h (stage-1 A operand, M=oo), 16 chunks x 2048 u32, m16n8k16 A-frag order:
//   idx = ((oot*4 + kk)*32 + lane)*4 + ra   (oot = oo tile of 16, [0,4))
//   oo = oot*16 + (lane>>2) + 8*(ra&1); half2 = m = kk*16 + 2*(lane&3) + 8*(ra>>1) + {0,1}
// gW23h (stage-2 A operand, M=o23), same shape:
//   o23 = mt*16 + (lane>>2) + 8*(ra&1); half2 = q = kk*16 + 2*(lane&3) + 8*(ra>>1) + {0,1}
__device__ __align__(16) uint32_t gW01h[32768];
__device__ __align__(16) uint32_t gW23h[32768];

__global__ void tt_pre(const float* __restrict__ w0, const float* __restrict__ w1,
                       const float* __restrict__ w2, const float* __restrict__ w3) {
    int tid = blockIdx.x * blockDim.x + threadIdx.x;
    if (tid < 32768) {
        int c    = tid >> 11;
        int rem  = tid & 2047;
        int ra   = rem & 3;
        int lane = (rem >> 2) & 31;
        int kk   = (rem >> 7) & 3;
        int oot  = rem >> 9;
        int oo   = oot*16 + (lane >> 2) + 8*(ra & 1);
        int mb   = kk*16 + 2*(lane & 3) + 8*(ra >> 1);
        int o0 = oo >> 3, o1 = oo & 7;
        float s[2];
        #pragma unroll
        for (int h = 0; h < 2; h++) {
            int m = mb + h;
            int i0 = m >> 3, i1 = m & 7;
            float v = 0.f;
            #pragma unroll
            for (int r1 = 0; r1 < 16; r1++)
                v += w0[(o0*16 + r1)*8 + i0] * w1[(o1*16 + c)*128 + r1*8 + i1];
            s[h] = v;
        }
        gW01h[c*2048 + rem] = packh2(s[0], s[1]);
    } else if (tid < 65536) {
        int t    = tid - 32768;
        int c    = t >> 11;
        int rem  = t & 2047;
        int ra   = rem & 3;
        int lane = (rem >> 2) & 31;
        int kk   = (rem >> 7) & 3;
        int mt   = rem >> 9;
        int o23  = mt*16 + (lane >> 2) + 8*(ra & 1);
        int qb   = kk*16 + 2*(lane & 3) + 8*(ra >> 1);
        int o2 = o23 >> 3, o3 = o23 & 7;
        float s[2];
        #pragma unroll
        for (int h = 0; h < 2; h++) {
            int q = qb + h;
            int i2 = q >> 3, i3 = q & 7;
            float v = 0.f;
            #pragma unroll
            for (int r3 = 0; r3 < 16; r3++)
                v += w2[(o2*16 + r3)*128 + c*8 + i2] * w3[o3*128 + r3*8 + i3];
            s[h] = v;
        }
        gW23h[c*2048 + rem] = packh2(s[0], s[1]);
    }
}

// ---------------- SMEM map (uint32 indices), 80 KB/CTA -> 2 CTAs/SM ----------------
// XH [0, 4096)       : X B-fragments fp16 (bank-swizzled), 2 batches x 2048 u32
// WH [4096, +16384)  : 4 chunk-slots x 4096 u32 (W01 at +0, W23 at +2048)
//                      reused post-loop as per-warp epilogue staging (2176 floats/warp)
#define W_OFF 4096
#define SMU_TOTAL 20480

__global__ __launch_bounds__(THREADS, 2)
void tt_mma(const float* __restrict__ x, const float* __restrict__ bias,
            float* __restrict__ out) {
    extern __shared__ uint32_t smu[];
    uint32_t* XH = smu;
    uint32_t* WH = smu + W_OFF;

    const int tid  = threadIdx.x;
    const int wid  = tid >> 5;
    const int lane = tid & 31;
    const uint32_t sb = smem_u32(smu);
    const uint32_t Wa = sb + W_OFF*4u;

    // ---- prologue: issue weight windows 0 (chunks 0,1) and 1 (chunks 2,3) ----
    #pragma unroll
    for (int g = 0; g < 2; g++) {
        #pragma unroll
        for (int cc = 0; cc < 2; cc++) {
            const int c = g*2 + cc;           // slot = c (c < 4)
            const uint4* s01 = (const uint4*)(gW01h + c*2048);
            const uint4* s23 = (const uint4*)(gW23h + c*2048);
            #pragma unroll
            for (int i = 0; i < 4; i++) {
                CPA16(Wa + c*16384u + (tid + i*128)*16, s01 + tid + i*128);
                CPA16(Wa + c*16384u + 8192u + (tid + i*128)*16, s23 + tid + i*128);
            }
        }
        CPA_COMMIT();
    }

    // ---- stage X (2 batch rows) into B-fragment layout in smem ----
    const long long b0 = (long long)blockIdx.x * 2;
    {
        const float4* xp = (const float4*)(x + b0 * 4096);
        #pragma unroll 4
        for (int e = tid; e < 1024; e += THREADS) {
            int u  = e & 31;              // m-pair index: m = 2u, 2u+1
            int qq = (e >> 5) & 15;       // q quad
            int b  = e >> 9;              // batch row (0..1)
            float4 va = xp[b*1024 + (2*u)*16 + qq];
            float4 vb = xp[b*1024 + (2*u + 1)*16 + qq];
            int kk = u >> 3;
            int rb = (u >> 2) & 1;
            int a3 = u & 3;
            float av[4] = {va.x, va.y, va.z, va.w};
            float bv[4] = {vb.x, vb.y, vb.z, vb.w};
            #pragma unroll
            for (int j = 0; j < 4; j++) {
                int q   = qq*4 + j;
                int nt1 = q >> 3;
                int ln  = ((q & 7)*4 + a3 + 8*kk) & 31;   // swizzled physical lane
                XH[(((b*8 + nt1)*4 + kk)*32 + ln)*2 + rb] = packh2(av[j], bv[j]);
            }
        }
    }

    CPA_WAIT1();        // window 0 weights complete (window 1 may be in flight)
    __syncthreads();    // X + window-0 weights visible CTA-wide

    // warp -> (batch bw, oo-half ooh): warp owns FULL q, 32 oo cols
    const int bw  = wid >> 1;
    const int ooh = wid & 1;

    // ---- this warp's X B-fragments in registers (chunk-invariant) ----
    uint32_t xr[4][8][2];
    #pragma unroll
    for (int kk = 0; kk < 4; kk++) {
        const int ln = (lane + 8*kk) & 31;
        #pragma unroll
        for (int nt1 = 0; nt1 < 8; nt1++) {
            uint2 bf = *(const uint2*)(XH + (((bw*8 + nt1)*4 + kk)*32 + ln)*2);
            xr[kk][nt1][0] = bf.x;
            xr[kk][nt1][1] = bf.y;
        }
    }

    float acc[4][4][4];
    #pragma unroll
    for (int mt = 0; mt < 4; mt++)
        #pragma unroll
        for (int ntl = 0; ntl < 4; ntl++)
            #pragma unroll
            for (int r = 0; r < 4; r++) acc[mt][ntl][r] = 0.f;

    for (int w = 0; w < 8; w++) {          // 2-chunk windows
        #pragma unroll
        for (int cc = 0; cc < 2; cc++) {
            const int c = 2*w + cc;
            const uint32_t* W01s = WH + (c & 3)*4096;
            const uint32_t* W23s = W01s + 2048;

            // ---- stage 1: dT[oo(32) x q(64)] = W01_c(A) @ X(B, registers) ----
            float d[2][8][4];
            #pragma unroll
            for (int mt1 = 0; mt1 < 2; mt1++)
                #pragma unroll
                for (int nt1 = 0; nt1 < 8; nt1++)
                    #pragma unroll
                    for (int r = 0; r < 4; r++) d[mt1][nt1][r] = 0.f;

            #pragma unroll
            for (int kk = 0; kk < 4; kk++) {
                #pragma unroll
                for (int mt1 = 0; mt1 < 2; mt1++) {
                    const int oot = ooh*2 + mt1;
                    uint4 af = *(const uint4*)(W01s + ((oot*4 + kk)*32 + lane)*4);
                    uint32_t a[4] = {af.x, af.y, af.z, af.w};
                    #pragma unroll
                    for (int nt1 = 0; nt1 < 8; nt1++)
                        mma16816(d[mt1][nt1], a, xr[kk][nt1][0], xr[kk][nt1][1]);
                }
            }

            // ---- stage 2: ACC[o23(64) x oo(32)] += W23_c(A) @ dT(B from C-frags) ----
            #pragma unroll
            for (int K = 0; K < 4; K++) {
                uint4 af[4];
                #pragma unroll
                for (int mt = 0; mt < 4; mt++)
                    af[mt] = *(const uint4*)(W23s + ((mt*4 + K)*32 + lane)*4);
                uint32_t bs[4][2];
                #pragma unroll
                for (int mt1 = 0; mt1 < 2; mt1++) {
                    bs[mt1*2 + 0][0] = packh2(d[mt1][2*K][0],     d[mt1][2*K][1]);
                    bs[mt1*2 + 0][1] = packh2(d[mt1][2*K + 1][0], d[mt1][2*K + 1][1]);
                    bs[mt1*2 + 1][0] = packh2(d[mt1][2*K][2],     d[mt1][2*K][3]);
                    bs[mt1*2 + 1][1] = packh2(d[mt1][2*K + 1][2], d[mt1][2*K + 1][3]);
                }
                #pragma unroll
                for (int mt = 0; mt < 4; mt++) {
                    uint32_t a[4] = {af[mt].x, af[mt].y, af[mt].z, af[mt].w};
                    #pragma unroll
                    for (int ntl = 0; ntl < 4; ntl++)
                        mma16816(acc[mt][ntl], a, bs[ntl][0], bs[ntl][1]);
                }
            }
        }

        // ---- window boundary: one barrier, then batch-issue window w+2 ----
        if (w < 7) {
            CPA_WAIT0();        // window w+1 weights fully arrived
            __syncthreads();    // visibility + WAR: window-w slots now free
            if (w < 6) {        // issue chunks 2w+4, 2w+5 into freed slots
                #pragma unroll
                for (int cc = 0; cc < 2; cc++) {
                    const int nc = 2*w + 4 + cc;
                    const int sl = nc & 3;
                    const uint4* s01 = (const uint4*)(gW01h + nc*2048);
                    const uint4* s23 = (const uint4*)(gW23h + nc*2048);
                    #pragma unroll
                    for (int i = 0; i < 4; i++) {
                        CPA16(Wa + sl*16384u + (tid + i*128)*16, s01 + tid + i*128);
                        CPA16(Wa + sl*16384u + 8192u + (tid + i*128)*16, s23 + tid + i*128);
                    }
                }
                CPA_COMMIT();
            }
        }
    }

    // ---- epilogue: per-warp smem transpose (stride 68, conflict-free), coalesced STG ----
    {
        const int g = lane >> 2, tq = lane & 3;
        float* epi = (float*)WH + wid * 2176;   // 4 warps x 2176 floats = 34 KB < 64 KB
        #pragma unroll
        for (int mt = 0; mt < 4; mt++)
            #pragma unroll
            for (int ntl = 0; ntl < 4; ntl++)
                #pragma unroll
                for (int r = 0; r < 4; r++) {
                    int o23 = mt*16 + g + 8*(r >> 1);
                    int ool = ntl*8 + 2*tq + (r & 1);
                    epi[ool*68 + o23] = acc[mt][ntl][r];
                }
        __syncwarp();
        float* ob = out + (b0 + bw) * 4096 + ooh * 2048;
        const float* bb = bias + ooh * 2048;
        #pragma unroll
        for (int i = 0; i < 16; i++) {
            int f = i*128 + lane*4;
            float4 v  = *(const float4*)(epi + f + 4*(f >> 6));
            float4 bv = *(const float4*)(bb + f);
            v.x += bv.x; v.y += bv.y; v.z += bv.z; v.w += bv.w;
            *(float4*)(ob + f) = v;
        }
    }
}

extern "C" void kernel_launch(void* const* d_in, const int* in_sizes, int n_in,
                              void* d_out, int out_size) {
    const float* x    = (const float*)d_in[0];
    const float* w0   = (const float*)d_in[1];
    const float* w1   = (const float*)d_in[2];
    const float* w2   = (const float*)d_in[3];
    const float* w3   = (const float*)d_in[4];
    const float* bias = (const float*)d_in[5];
    float* out = (float*)d_out;

    tt_pre<<<512, 128>>>(w0, w1, w2, w3);

    cudaFuncSetAttribute(tt_mma, cudaFuncAttributeMaxDynamicSharedMemorySize,
                         SMU_TOTAL * (int)sizeof(uint32_t));
    tt_mma<<<16384 / 2, THREADS, SMU_TOTAL * (int)sizeof(uint32_t)>>>(x, bias, out);
}

// round 17
// speedup vs baseline: 1.2126x; 1.0003x over previous
#include <cuda_runtime.h>
#include <cuda_fp16.h>
#include <cstdint>

#define THREADS 128

// ---------------- helpers ----------------
__device__ __forceinline__ uint32_t smem_u32(const void* p){
    uint32_t a;
    asm("{ .reg .u64 t; cvta.to.shared.u64 t, %1; cvt.u32.u64 %0, t; }" : "=r"(a) : "l"(p));
    return a;
}
__device__ __forceinline__ uint32_t packh2(float lo, float hi){
    __half2 h = __floats2half2_rn(lo, hi);
    return *reinterpret_cast<uint32_t*>(&h);
}
__device__ __forceinline__ void mma16816(float d[4], const uint32_t a[4],
                                         const uint32_t b0, const uint32_t b1){
    asm volatile("mma.sync.aligned.m16n8k16.row.col.f32.f16.f16.f32 "
        "{%0,%1,%2,%3}, {%4,%5,%6,%7}, {%8,%9}, {%0,%1,%2,%3};"
        : "+f"(d[0]), "+f"(d[1]), "+f"(d[2]), "+f"(d[3])
        : "r"(a[0]), "r"(a[1]), "r"(a[2]), "r"(a[3]), "r"(b0), "r"(b1));
}
#define CPA16(d, s)  asm volatile("cp.async.cg.shared.global [%0], [%1], 16;" :: "r"(d), "l"(s))
#define CPA_COMMIT() asm volatile("cp.async.commit_group;" ::: "memory")
#define CPA_WAIT0()  asm volatile("cp.async.wait_group 0;" ::: "memory")
#define CPA_WAIT1()  asm volatile("cp.async.wait_group 1;" ::: "memory")

// ---------------- merged weights, fp16 fragment-ordered (half2 = uint32) ----------------
// gW01h (stage-1 A operand, M=oo), 16 chunks x 2048 u32, m16n8k16 A-frag order:
//   idx = ((oot*4 + kk)*32 + lane)*4 + ra   (oot = oo tile of 16, [0,4))
//   oo = oot*16 + (lane>>2) + 8*(ra&1); half2 = m = kk*16 + 2*(lane&3) + 8*(ra>>1) + {0,1}
// gW23h (stage-2 A operand, M=o23), same shape:
//   o23 = mt*16 + (lane>>2) + 8*(ra&1); half2 = q = kk*16 + 2*(lane&3) + 8*(ra>>1) + {0,1}
__device__ __align__(16) uint32_t gW01h[32768];
__device__ __align__(16) uint32_t gW23h[32768];

__global__ void tt_pre(const float* __restrict__ w0, const float* __restrict__ w1,
                       const float* __restrict__ w2, const float* __restrict__ w3) {
    int tid = blockIdx.x * blockDim.x + threadIdx.x;
    if (tid < 32768) {
        int c    = tid >> 11;
        int rem  = tid & 2047;
        int ra   = rem & 3;
        int lane = (rem >> 2) & 31;
        int kk   = (rem >> 7) & 3;
        int oot  = rem >> 9;
        int oo   = oot*16 + (lane >> 2) + 8*(ra & 1);
        int mb   = kk*16 + 2*(lane & 3) + 8*(ra >> 1);
        int o0 = oo >> 3, o1 = oo & 7;
        float s[2];
        #pragma unroll
        for (int h = 0; h < 2; h++) {
            int m = mb + h;
            int i0 = m >> 3, i1 = m & 7;
            float v = 0.f;
            #pragma unroll
            for (int r1 = 0; r1 < 16; r1++)
                v += w0[(o0*16 + r1)*8 + i0] * w1[(o1*16 + c)*128 + r1*8 + i1];
            s[h] = v;
        }
        gW01h[c*2048 + rem] = packh2(s[0], s[1]);
    } else if (tid < 65536) {
        int t    = tid - 32768;
        int c    = t >> 11;
        int rem  = t & 2047;
        int ra   = rem & 3;
        int lane = (rem >> 2) & 31;
        int kk   = (rem >> 7) & 3;
        int mt   = rem >> 9;
        int o23  = mt*16 + (lane >> 2) + 8*(ra & 1);
        int qb   = kk*16 + 2*(lane & 3) + 8*(ra >> 1);
        int o2 = o23 >> 3, o3 = o23 & 7;
        float s[2];
        #pragma unroll
        for (int h = 0; h < 2; h++) {
            int q = qb + h;
            int i2 = q >> 3, i3 = q & 7;
            float v = 0.f;
            #pragma unroll
            for (int r3 = 0; r3 < 16; r3++)
                v += w2[(o2*16 + r3)*128 + c*8 + i2] * w3[o3*128 + r3*8 + i3];
            s[h] = v;
        }
        gW23h[c*2048 + rem] = packh2(s[0], s[1]);
    }
}

// ---------------- SMEM map (uint32 indices), 80 KB/CTA -> 2 CTAs/SM ----------------
// XH [0, 4096)       : X B-fragments fp16 (bank-swizzled), 2 batches x 2048 u32
// WH [4096, +16384)  : 4 chunk-slots x 4096 u32 (W01 at +0, W23 at +2048)
//                      reused post-loop as per-warp epilogue staging
#define W_OFF 4096
#define SMU_TOTAL 20480

__global__ __launch_bounds__(THREADS, 2)
void tt_mma(const float* __restrict__ x, const float* __restrict__ bias,
            float* __restrict__ out) {
    extern __shared__ uint32_t smu[];
    uint32_t* XH = smu;
    uint32_t* WH = smu + W_OFF;

    const int tid  = threadIdx.x;
    const int wid  = tid >> 5;
    const int lane = tid & 31;
    const uint32_t sb = smem_u32(smu);
    const uint32_t Wa = sb + W_OFF*4u;

    // ---- prologue: issue weight windows 0 (chunks 0,1) and 1 (chunks 2,3) ----
    #pragma unroll
    for (int g = 0; g < 2; g++) {
        #pragma unroll
        for (int cc = 0; cc < 2; cc++) {
            const int c = g*2 + cc;           // slot = c (c < 4)
            const uint4* s01 = (const uint4*)(gW01h + c*2048);
            const uint4* s23 = (const uint4*)(gW23h + c*2048);
            #pragma unroll
            for (int i = 0; i < 4; i++) {
                CPA16(Wa + c*16384u + (tid + i*128)*16, s01 + tid + i*128);
                CPA16(Wa + c*16384u + 8192u + (tid + i*128)*16, s23 + tid + i*128);
            }
        }
        CPA_COMMIT();
    }

    // ---- stage X (2 batch rows) into B-fragment layout in smem ----
    const long long b0 = (long long)blockIdx.x * 2;
    {
        const float4* xp = (const float4*)(x + b0 * 4096);
        #pragma unroll 4
        for (int e = tid; e < 1024; e += THREADS) {
            int u  = e & 31;              // m-pair index: m = 2u, 2u+1
            int qq = (e >> 5) & 15;       // q quad
            int b  = e >> 9;              // batch row (0..1)
            float4 va = xp[b*1024 + (2*u)*16 + qq];
            float4 vb = xp[b*1024 + (2*u + 1)*16 + qq];
            int kk = u >> 3;
            int rb = (u >> 2) & 1;
            int a3 = u & 3;
            float av[4] = {va.x, va.y, va.z, va.w};
            float bv[4] = {vb.x, vb.y, vb.z, vb.w};
            #pragma unroll
            for (int j = 0; j < 4; j++) {
                int q   = qq*4 + j;
                int nt1 = q >> 3;
                int ln  = ((q & 7)*4 + a3 + 8*kk) & 31;   // swizzled physical lane
                XH[(((b*8 + nt1)*4 + kk)*32 + ln)*2 + rb] = packh2(av[j], bv[j]);
            }
        }
    }

    CPA_WAIT1();        // window 0 weights complete (window 1 may be in flight)
    __syncthreads();    // X + window-0 weights visible CTA-wide

    // warp -> (batch bw, oo-half ooh): warp owns FULL q, 32 oo cols
    const int bw  = wid >> 1;
    const int ooh = wid & 1;

    // ---- this warp's X B-fragments in registers (chunk-invariant) ----
    uint32_t xr[4][8][2];
    #pragma unroll
    for (int kk = 0; kk < 4; kk++) {
        const int ln = (lane + 8*kk) & 31;
        #pragma unroll
        for (int nt1 = 0; nt1 < 8; nt1++) {
            uint2 bf = *(const uint2*)(XH + (((bw*8 + nt1)*4 + kk)*32 + ln)*2);
            xr[kk][nt1][0] = bf.x;
            xr[kk][nt1][1] = bf.y;
        }
    }

    float acc[4][4][4];
    #pragma unroll
    for (int mt = 0; mt < 4; mt++)
        #pragma unroll
        for (int ntl = 0; ntl < 4; ntl++)
            #pragma unroll
            for (int r = 0; r < 4; r++) acc[mt][ntl][r] = 0.f;

    for (int w = 0; w < 8; w++) {          // 2-chunk windows
        #pragma unroll
        for (int cc = 0; cc < 2; cc++) {
            const int c = 2*w + cc;
            const uint32_t* W01s = WH + (c & 3)*4096;
            const uint32_t* W23s = W01s + 2048;

            // ---- preload this chunk's W01 A-frags into registers (8 LDS.128) ----
            uint4 wa[2][4];   // [mt1][kk]
            #pragma unroll
            for (int mt1 = 0; mt1 < 2; mt1++) {
                const int oot = ooh*2 + mt1;
                #pragma unroll
                for (int kk = 0; kk < 4; kk++)
                    wa[mt1][kk] = *(const uint4*)(W01s + ((oot*4 + kk)*32 + lane)*4);
            }

            // ---- interleaved: per q-pair P, stage1 block then stage2 block ----
            #pragma unroll
            for (int P = 0; P < 4; P++) {
                // stage 1 block: d[mt1][p] for q-tiles nt1 = 2P, 2P+1 (16 MMAs)
                float d[2][2][4];
                #pragma unroll
                for (int mt1 = 0; mt1 < 2; mt1++)
                    #pragma unroll
                    for (int p = 0; p < 2; p++)
                        #pragma unroll
                        for (int r = 0; r < 4; r++) d[mt1][p][r] = 0.f;

                #pragma unroll
                for (int kk = 0; kk < 4; kk++)
                    #pragma unroll
                    for (int mt1 = 0; mt1 < 2; mt1++) {
                        uint32_t a[4] = {wa[mt1][kk].x, wa[mt1][kk].y,
                                         wa[mt1][kk].z, wa[mt1][kk].w};
                        mma16816(d[mt1][0], a, xr[kk][2*P][0],   xr[kk][2*P][1]);
                        mma16816(d[mt1][1], a, xr[kk][2*P+1][0], xr[kk][2*P+1][1]);
                    }

                // stage 2 block: K = P (af preload hides LDS under the packs)
                uint4 af[4];
                #pragma unroll
                for (int mt = 0; mt < 4; mt++)
                    af[mt] = *(const uint4*)(W23s + ((mt*4 + P)*32 + lane)*4);
                uint32_t bs[4][2];
                #pragma unroll
                for (int mt1 = 0; mt1 < 2; mt1++) {
                    bs[mt1*2 + 0][0] = packh2(d[mt1][0][0], d[mt1][0][1]);
                    bs[mt1*2 + 0][1] = packh2(d[mt1][1][0], d[mt1][1][1]);
                    bs[mt1*2 + 1][0] = packh2(d[mt1][0][2], d[mt1][0][3]);
                    bs[mt1*2 + 1][1] = packh2(d[mt1][1][2], d[mt1][1][3]);
                }
                #pragma unroll
                for (int mt = 0; mt < 4; mt++) {
                    uint32_t a[4] = {af[mt].x, af[mt].y, af[mt].z, af[mt].w};
                    #pragma unroll
                    for (int ntl = 0; ntl < 4; ntl++)
                        mma16816(acc[mt][ntl], a, bs[ntl][0], bs[ntl][1]);
                }
            }
        }

        // ---- window boundary: one barrier, then batch-issue window w+2 ----
        if (w < 7) {
            CPA_WAIT0();        // window w+1 weights fully arrived
            __syncthreads();    // visibility + WAR: window-w slots now free
            if (w < 6) {        // issue chunks 2w+4, 2w+5 into freed slots
                #pragma unroll
                for (int cc = 0; cc < 2; cc++) {
                    const int nc = 2*w + 4 + cc;
                    const int sl = nc & 3;
                    const uint4* s01 = (const uint4*)(gW01h + nc*2048);
                    const uint4* s23 = (const uint4*)(gW23h + nc*2048);
                    #pragma unroll
                    for (int i = 0; i < 4; i++) {
                        CPA16(Wa + sl*16384u + (tid + i*128)*16, s01 + tid + i*128);
                        CPA16(Wa + sl*16384u + 8192u + (tid + i*128)*16, s23 + tid + i*128);
                    }
                }
                CPA_COMMIT();
            }
        }
    }

    // ---- epilogue: per-warp smem transpose (stride 68, conflict-free), coalesced STG ----
    {
        const int g = lane >> 2, tq = lane & 3;
        float* epi = (float*)WH + wid * 2176;   // 4 warps x 2176 floats = 34 KB < 64 KB
        #pragma unroll
        for (int mt = 0; mt < 4; mt++)
            #pragma unroll
            for (int ntl = 0; ntl < 4; ntl++)
                #pragma unroll
                for (int r = 0; r < 4; r++) {
                    int o23 = mt*16 + g + 8*(r >> 1);
                    int ool = ntl*8 + 2*tq + (r & 1);
                    epi[ool*68 + o23] = acc[mt][ntl][r];
                }
        __syncwarp();
        float* ob = out + (b0 + bw) * 4096 + ooh * 2048;
        const float* bb = bias + ooh * 2048;
        #pragma unroll
        for (int i = 0; i < 16; i++) {
            int f = i*128 + lane*4;
            float4 v  = *(const float4*)(epi + f + 4*(f >> 6));
            float4 bv = *(const float4*)(bb + f);
            v.x += bv.x; v.y += bv.y; v.z += bv.z; v.w += bv.w;
            *(float4*)(ob + f) = v;
        }
    }
}

extern "C" void kernel_launch(void* const* d_in, const int* in_sizes, int n_in,
                              void* d_out, int out_size) {
    const float* x    = (const float*)d_in[0];
    const float* w0   = (const float*)d_in[1];
    const float* w1   = (const float*)d_in[2];
    const float* w2   = (const float*)d_in[3];
    const float* w3   = (const float*)d_in[4];
    const float* bias = (const float*)d_in[5];
    float* out = (float*)d_out;

    tt_pre<<<512, 128>>>(w0, w1, w2, w3);

    cudaFuncSetAttribute(tt_mma, cudaFuncAttributeMaxDynamicSharedMemorySize,
                         SMU_TOTAL * (int)sizeof(uint32_t));
    tt_mma<<<16384 / 2, THREADS, SMU_TOTAL * (int)sizeof(uint32_t)>>>(x, bias, out);
}